// round 1
// baseline (speedup 1.0000x reference)
#include <cuda_runtime.h>
#include <cuda_bf16.h>

// Problem constants
#define BATCH      32
#define DIM        64
#define HW         4096          // 64*64
#define NPIX       131072        // 32*4096
#define KCODES     512
#define PIXPB      128           // pixels per block
#define NBLOCKS    1024          // NPIX / PIXPB
#define THREADS    256
#define KCHUNK     128
#define NCHUNK     4             // KCODES / KCHUNK
#define RSTR       132           // smem row stride (128 + 4 pad, 16B aligned)
#define QOFF       131072        // quantized offset in d_out (floats)
#define LOFF       8519680       // loss offset = 131072 + 8388608
#define NELEM_Q    8388608.0

__device__ double g_loss;
__device__ float  g_wsq[KCODES];

// ---------------------------------------------------------------------------
// init: zero loss accumulator, precompute ||w_k||^2 (reference rounding:
// products rounded, sequential adds)
// ---------------------------------------------------------------------------
__global__ void vq_init(const float* __restrict__ wt) {
    int k = threadIdx.x;
    if (k == 0) g_loss = 0.0;
    if (k < KCODES) {
        const float* w = wt + k * DIM;
        float c = 0.0f;
        #pragma unroll 8
        for (int d = 0; d < DIM; ++d)
            c = __fadd_rn(c, __fmul_rn(w[d], w[d]));
        g_wsq[k] = c;
    }
}

// ---------------------------------------------------------------------------
// main: fused distance-GEMM + argmin + gather + ST output + loss partial
// ---------------------------------------------------------------------------
__global__ __launch_bounds__(THREADS, 2)
void vq_main(const float* __restrict__ in, const float* __restrict__ wt,
             float* __restrict__ out) {
    extern __shared__ float sm[];
    float* Xs = sm;                   // [64][RSTR], Xs[d][j] = x of pixel j, dim d
    float* Ws = sm + DIM * RSTR;      // [64][RSTR], Ws[d][k] = w of code k, dim d

    __shared__ float cs[PIXPB];       // ||x||^2 per pixel
    __shared__ int   idxs[PIXPB];     // final argmin per pixel
    __shared__ float wsqs[KCODES];
    __shared__ float warp_part[8];

    const int tid   = threadIdx.x;
    const int pbase = blockIdx.x * PIXPB;
    const int b     = pbase >> 12;            // pbase / 4096
    const int hw    = pbase & 4095;
    const float* inb = in + (size_t)b * (DIM * HW) + hw;

    // Load X tile: coalesced gmem, conflict-free smem
    for (int i = tid; i < DIM * PIXPB; i += THREADS) {
        int d = i >> 7, j = i & 127;
        Xs[d * RSTR + j] = inb[d * HW + j];
    }
    for (int i = tid; i < KCODES; i += THREADS) wsqs[i] = g_wsq[i];
    __syncthreads();

    // ||x||^2 per pixel: product-rounded, sequential sum (mimic sum(flat*flat))
    if (tid < PIXPB) {
        float c = 0.0f;
        #pragma unroll 8
        for (int d = 0; d < DIM; ++d) {
            float x = Xs[d * RSTR + tid];
            c = __fadd_rn(c, __fmul_rn(x, x));
        }
        cs[tid] = c;
    }

    const int ty = tid >> 4;   // 0..15 : pixel group (8 pixels)
    const int tx = tid & 15;   // 0..15 : code group (8 codes within chunk)

    float bs[8];
    int   bi[8];
    #pragma unroll
    for (int i = 0; i < 8; ++i) { bs[i] = __int_as_float(0x7f800000); bi[i] = 0; }

    for (int ch = 0; ch < NCHUNK; ++ch) {
        __syncthreads();   // protect Ws reuse
        // Load W chunk transposed: Ws[d][k_local] = wt[(ch*128+k)*64 + d]
        for (int i = tid; i < KCHUNK * DIM; i += THREADS) {
            int k = i >> 6, d = i & 63;
            Ws[d * RSTR + k] = wt[(ch * KCHUNK + k) * DIM + d];
        }
        __syncthreads();

        float acc[8][8];
        #pragma unroll
        for (int i = 0; i < 8; ++i)
            #pragma unroll
            for (int j = 0; j < 8; ++j) acc[i][j] = 0.0f;

        #pragma unroll 2
        for (int d = 0; d < DIM; ++d) {
            const float4 xa = *reinterpret_cast<const float4*>(Xs + d * RSTR + ty * 8);
            const float4 xb = *reinterpret_cast<const float4*>(Xs + d * RSTR + ty * 8 + 4);
            const float4 wa = *reinterpret_cast<const float4*>(Ws + d * RSTR + tx * 8);
            const float4 wb = *reinterpret_cast<const float4*>(Ws + d * RSTR + tx * 8 + 4);
            float xr[8] = {xa.x, xa.y, xa.z, xa.w, xb.x, xb.y, xb.z, xb.w};
            float wr[8] = {wa.x, wa.y, wa.z, wa.w, wb.x, wb.y, wb.z, wb.w};
            #pragma unroll
            for (int i = 0; i < 8; ++i)
                #pragma unroll
                for (int j = 0; j < 8; ++j)
                    acc[i][j] = __fmaf_rn(xr[i], wr[j], acc[i][j]);
        }

        // Argmin update — ascending k within thread, strict < keeps first min,
        // exact reference rounding: fl(fl(c - 2*dot) + wsq)
        #pragma unroll
        for (int i = 0; i < 8; ++i) {
            const float c = cs[ty * 8 + i];
            #pragma unroll
            for (int j = 0; j < 8; ++j) {
                int k = ch * KCHUNK + tx * 8 + j;
                float s = __fadd_rn(__fsub_rn(c, 2.0f * acc[i][j]), wsqs[k]);
                if (s < bs[i]) { bs[i] = s; bi[i] = k; }
            }
        }
    }

    // Cross-thread argmin reduction (reuse Ws region): 128 pixels x 16 lanes
    __syncthreads();
    float2* red = reinterpret_cast<float2*>(Ws);
    #pragma unroll
    for (int i = 0; i < 8; ++i)
        red[(ty * 8 + i) * 16 + tx] = make_float2(bs[i], __int_as_float(bi[i]));
    __syncthreads();

    if (tid < PIXPB) {
        float best = __int_as_float(0x7f800000);
        int   bk   = 0x7fffffff;
        #pragma unroll
        for (int t = 0; t < 16; ++t) {
            float2 e = red[tid * 16 + t];
            float s = e.x; int k = __float_as_int(e.y);
            if (s < best || (s == best && k < bk)) { best = s; bk = k; }
        }
        idxs[tid] = bk;
        out[pbase + tid] = (float)bk;    // discrete_latent (as fp32)
    }
    __syncthreads();

    // Epilogue: quantized (straight-through rounding!) + loss partial
    float* outq = out + QOFF + (size_t)b * (DIM * HW) + hw;
    float lsum = 0.0f;
    for (int i = tid; i < DIM * PIXPB; i += THREADS) {
        int d = i >> 7, j = i & 127;
        int k = idxs[j];
        float q = wt[k * DIM + d];
        float x = Xs[d * RSTR + j];
        float df = __fsub_rn(q, x);
        lsum = __fmaf_rn(df, df, lsum);
        outq[d * HW + j] = __fadd_rn(x, df);   // x + (q - x), fp32-rounded like ref
    }
    #pragma unroll
    for (int off = 16; off > 0; off >>= 1)
        lsum += __shfl_down_sync(0xffffffffu, lsum, off);
    if ((tid & 31) == 0) warp_part[tid >> 5] = lsum;
    __syncthreads();
    if (tid == 0) {
        float tot = 0.0f;
        #pragma unroll
        for (int w = 0; w < 8; ++w) tot += warp_part[w];
        atomicAdd(&g_loss, (double)tot);
    }
}

// ---------------------------------------------------------------------------
// finalize: loss = m + 0.25*m,  m = mean((q - x)^2)
// ---------------------------------------------------------------------------
__global__ void vq_fin(float* __restrict__ out) {
    double m = g_loss / NELEM_Q;
    out[LOFF] = (float)(m + 0.25 * m);
}

extern "C" void kernel_launch(void* const* d_in, const int* in_sizes, int n_in,
                              void* d_out, int out_size) {
    (void)in_sizes; (void)n_in; (void)out_size;
    const float* in = (const float*)d_in[0];
    const float* wt = (const float*)d_in[1];
    float* out = (float*)d_out;

    const int smem = 2 * DIM * RSTR * sizeof(float);   // 67584 B
    cudaFuncSetAttribute(vq_main, cudaFuncAttributeMaxDynamicSharedMemorySize, smem);

    vq_init<<<1, 512>>>(wt);
    vq_main<<<NBLOCKS, THREADS, smem>>>(in, wt, out);
    vq_fin<<<1, 1>>>(out);
}

// round 2
// speedup vs baseline: 1.2611x; 1.2611x over previous
#include <cuda_runtime.h>
#include <cuda_bf16.h>

// Problem constants
#define BATCH      32
#define DIM        64
#define HW         4096          // 64*64
#define NPIX       131072        // 32*4096
#define KCODES     512
#define PIXPB      128           // pixels per block
#define NBLOCKS    1024          // NPIX / PIXPB
#define THREADS    256
#define KCHUNK     128
#define NCHUNK     4             // KCODES / KCHUNK
#define RSTR       132           // smem row stride (128 + 4 pad, 16B aligned)
#define QOFF       131072        // quantized offset in d_out (floats)
#define LOFF       8519680       // loss offset = 131072 + 8388608
#define NELEM_Q    8388608.0

__device__ double g_loss;
__device__ float  g_wsq[KCODES];

// ---- packed fp32 helpers (each lane is an exact fp32 rn op) ------------
__device__ __forceinline__ unsigned long long ffma2(unsigned long long a,
                                                    unsigned long long b,
                                                    unsigned long long c) {
    unsigned long long d;
    asm("fma.rn.f32x2 %0, %1, %2, %3;" : "=l"(d) : "l"(a), "l"(b), "l"(c));
    return d;
}
__device__ __forceinline__ unsigned long long dup2(float x) {
    unsigned long long d;
    asm("mov.b64 %0, {%1, %1};" : "=l"(d) : "f"(x));
    return d;
}
__device__ __forceinline__ unsigned long long pack2(float lo, float hi) {
    unsigned long long d;
    asm("mov.b64 %0, {%1, %2};" : "=l"(d) : "f"(lo), "f"(hi));
    return d;
}
__device__ __forceinline__ float2 unpack2(unsigned long long v) {
    float lo, hi;
    asm("mov.b64 {%0, %1}, %2;" : "=f"(lo), "=f"(hi) : "l"(v));
    return make_float2(lo, hi);
}

// ---------------------------------------------------------------------------
// init: zero loss accumulator, precompute ||w_k||^2 with reference rounding
// (product rounded, sequential adds). 4 blocks x 128 threads, smem-staged.
// ---------------------------------------------------------------------------
__global__ void vq_init(const float* __restrict__ wt) {
    __shared__ float w[128][65];
    const int tid  = threadIdx.x;
    const int base = blockIdx.x * 128;
    if (blockIdx.x == 0 && tid == 0) g_loss = 0.0;
    for (int i = tid; i < 128 * DIM; i += 128) {
        int k = i >> 6, d = i & 63;
        w[k][d] = wt[(base + k) * DIM + d];
    }
    __syncthreads();
    float c = 0.0f;
    #pragma unroll 8
    for (int d = 0; d < DIM; ++d)
        c = __fadd_rn(c, __fmul_rn(w[tid][d], w[tid][d]));
    g_wsq[base + tid] = c;
}

// ---------------------------------------------------------------------------
// main: fused distance-GEMM (packed FFMA2) + argmin + gather + ST + loss
// ---------------------------------------------------------------------------
__global__ __launch_bounds__(THREADS, 2)
void vq_main(const float* __restrict__ in, const float* __restrict__ wt,
             float* __restrict__ out) {
    extern __shared__ float sm[];
    float* Xs = sm;                   // [64][RSTR], Xs[d][j] = x of pixel j, dim d
    float* Ws = sm + DIM * RSTR;      // [64][RSTR], Ws[d][k] = w of code k, dim d

    __shared__ float cs[PIXPB];       // ||x||^2 per pixel
    __shared__ int   idxs[PIXPB];     // final argmin per pixel
    __shared__ float wsqs[KCODES];
    __shared__ float warp_part[8];

    const int tid   = threadIdx.x;
    const int pbase = blockIdx.x * PIXPB;
    const int b     = pbase >> 12;            // pbase / 4096
    const int hw    = pbase & 4095;
    const float* inb = in + (size_t)b * (DIM * HW) + hw;

    // Load X tile: coalesced gmem, conflict-free smem
    for (int i = tid; i < DIM * PIXPB; i += THREADS) {
        int d = i >> 7, j = i & 127;
        Xs[d * RSTR + j] = inb[d * HW + j];
    }
    for (int i = tid; i < KCODES; i += THREADS) wsqs[i] = g_wsq[i];
    __syncthreads();

    // ||x||^2 per pixel: product-rounded, sequential sum (mimic sum(flat*flat))
    if (tid < PIXPB) {
        float c = 0.0f;
        #pragma unroll 8
        for (int d = 0; d < DIM; ++d) {
            float x = Xs[d * RSTR + tid];
            c = __fadd_rn(c, __fmul_rn(x, x));
        }
        cs[tid] = c;
    }

    const int ty = tid >> 4;   // 0..15 : pixel group (8 pixels)
    const int tx = tid & 15;   // 0..15 : code group (8 codes within chunk)

    float bs[8];
    int   bi[8];
    #pragma unroll
    for (int i = 0; i < 8; ++i) { bs[i] = __int_as_float(0x7f800000); bi[i] = 0; }

    for (int ch = 0; ch < NCHUNK; ++ch) {
        __syncthreads();   // protect Ws reuse
        // Load W chunk transposed: Ws[d][k_local] = wt[(ch*128+k)*64 + d]
        for (int i = tid; i < KCHUNK * DIM; i += THREADS) {
            int k = i >> 6, d = i & 63;
            Ws[d * RSTR + k] = wt[(ch * KCHUNK + k) * DIM + d];
        }
        __syncthreads();

        // accp[pixel][codepair] : lanes = (code 2jj, code 2jj+1), exact fp32
        unsigned long long accp[8][4];
        #pragma unroll
        for (int i = 0; i < 8; ++i)
            #pragma unroll
            for (int jj = 0; jj < 4; ++jj) accp[i][jj] = 0ull;

        #pragma unroll 2
        for (int d = 0; d < DIM; ++d) {
            const float4 xa = *reinterpret_cast<const float4*>(Xs + d * RSTR + ty * 8);
            const float4 xb = *reinterpret_cast<const float4*>(Xs + d * RSTR + ty * 8 + 4);
            const float4 wa = *reinterpret_cast<const float4*>(Ws + d * RSTR + tx * 8);
            const float4 wb = *reinterpret_cast<const float4*>(Ws + d * RSTR + tx * 8 + 4);
            unsigned long long wp[4];
            wp[0] = pack2(wa.x, wa.y);
            wp[1] = pack2(wa.z, wa.w);
            wp[2] = pack2(wb.x, wb.y);
            wp[3] = pack2(wb.z, wb.w);
            float xr[8] = {xa.x, xa.y, xa.z, xa.w, xb.x, xb.y, xb.z, xb.w};
            #pragma unroll
            for (int i = 0; i < 8; ++i) {
                const unsigned long long xd = dup2(xr[i]);
                #pragma unroll
                for (int jj = 0; jj < 4; ++jj)
                    accp[i][jj] = ffma2(xd, wp[jj], accp[i][jj]);
            }
        }

        // Argmin update — ascending k, strict < keeps first min,
        // exact reference rounding: fl(fl(c - 2*dot) + wsq)
        #pragma unroll
        for (int i = 0; i < 8; ++i) {
            const float c = cs[ty * 8 + i];
            #pragma unroll
            for (int jj = 0; jj < 4; ++jj) {
                float2 dot = unpack2(accp[i][jj]);
                int k0 = ch * KCHUNK + tx * 8 + jj * 2;
                float s0 = __fadd_rn(__fsub_rn(c, 2.0f * dot.x), wsqs[k0]);
                if (s0 < bs[i]) { bs[i] = s0; bi[i] = k0; }
                float s1 = __fadd_rn(__fsub_rn(c, 2.0f * dot.y), wsqs[k0 + 1]);
                if (s1 < bs[i]) { bs[i] = s1; bi[i] = k0 + 1; }
            }
        }
    }

    // Cross-thread argmin reduction (reuse Ws region): 128 pixels x 16 lanes
    __syncthreads();
    float2* red = reinterpret_cast<float2*>(Ws);
    #pragma unroll
    for (int i = 0; i < 8; ++i)
        red[(ty * 8 + i) * 16 + tx] = make_float2(bs[i], __int_as_float(bi[i]));
    __syncthreads();

    if (tid < PIXPB) {
        float best = __int_as_float(0x7f800000);
        int   bk   = 0x7fffffff;
        #pragma unroll
        for (int t = 0; t < 16; ++t) {
            float2 e = red[tid * 16 + t];
            float s = e.x; int k = __float_as_int(e.y);
            if (s < best || (s == best && k < bk)) { best = s; bk = k; }
        }
        idxs[tid] = bk;
        out[pbase + tid] = (float)bk;    // discrete_latent (as fp32)
    }
    __syncthreads();

    // Epilogue: quantized (straight-through rounding!) + loss partial
    float* outq = out + QOFF + (size_t)b * (DIM * HW) + hw;
    float lsum = 0.0f;
    for (int i = tid; i < DIM * PIXPB; i += THREADS) {
        int d = i >> 7, j = i & 127;
        int k = idxs[j];
        float q = wt[k * DIM + d];
        float x = Xs[d * RSTR + j];
        float df = __fsub_rn(q, x);
        lsum = __fmaf_rn(df, df, lsum);
        outq[d * HW + j] = __fadd_rn(x, df);   // x + (q - x), fp32-rounded like ref
    }
    #pragma unroll
    for (int off = 16; off > 0; off >>= 1)
        lsum += __shfl_down_sync(0xffffffffu, lsum, off);
    if ((tid & 31) == 0) warp_part[tid >> 5] = lsum;
    __syncthreads();
    if (tid == 0) {
        float tot = 0.0f;
        #pragma unroll
        for (int w = 0; w < 8; ++w) tot += warp_part[w];
        atomicAdd(&g_loss, (double)tot);
    }
}

// ---------------------------------------------------------------------------
// finalize: loss = m + 0.25*m,  m = mean((q - x)^2)
// ---------------------------------------------------------------------------
__global__ void vq_fin(float* __restrict__ out) {
    double m = g_loss / NELEM_Q;
    out[LOFF] = (float)(m + 0.25 * m);
}

extern "C" void kernel_launch(void* const* d_in, const int* in_sizes, int n_in,
                              void* d_out, int out_size) {
    (void)in_sizes; (void)n_in; (void)out_size;
    const float* in = (const float*)d_in[0];
    const float* wt = (const float*)d_in[1];
    float* out = (float*)d_out;

    const int smem = 2 * DIM * RSTR * sizeof(float);   // 67584 B
    cudaFuncSetAttribute(vq_main, cudaFuncAttributeMaxDynamicSharedMemorySize, smem);

    vq_init<<<4, 128>>>(wt);
    vq_main<<<NBLOCKS, THREADS, smem>>>(in, wt, out);
    vq_fin<<<1, 1>>>(out);
}